// round 4
// baseline (speedup 1.0000x reference)
#include <cuda_runtime.h>

// SNNLayer, R4: multi-cell warps with cross-cell load overlap.
//
//   d_in[0] x              : (256,256,1,32)
//   d_in[1] input_matrix   : (256,256,32,32)
//   d_in[2] layer_weights  : (4,256,256,32,32)
//   out                    : (256,256,1,32)
//
// One warp per 4 consecutive cells; lane l = (r=l>>3, c=l&7). All cross-lane
// traffic is SHFL (no smem, no barriers). The cell loop is unrolled 2x so
// cell j+1's independent LDG.128 batch can issue while cell j sits in its
// shfl-reduction dependency chain — removing the per-cell load-silent window
// that capped R3 at 92.3% DRAM.

#define NCELLS   65536
#define NDIM     32
#define MAT_F4   256            // 1024 floats = 256 float4
#define CELLS_PER_WARP 4
#define WARPS_PER_BLOCK 8
#define THREADS  (WARPS_PER_BLOCK * 32)
#define BLOCKS   (NCELLS / (WARPS_PER_BLOCK * CELLS_PER_WARP))   // 2048
#define DECAY    0.8f
#define FULLMASK 0xFFFFFFFFu

__device__ __forceinline__ void reduce_xor(float4& a)
{
#pragma unroll
    for (int m = 8; m <= 16; m <<= 1) {
        a.x += __shfl_xor_sync(FULLMASK, a.x, m);
        a.y += __shfl_xor_sync(FULLMASK, a.y, m);
        a.z += __shfl_xor_sync(FULLMASK, a.z, m);
        a.w += __shfl_xor_sync(FULLMASK, a.w, m);
    }
}

__global__ __launch_bounds__(THREADS, 4)
void snn_layer_kernel(const float* __restrict__ x,
                      const float4* __restrict__ input_matrix,
                      const float4* __restrict__ layer_weights,
                      float4* __restrict__ out)
{
    const int lane = threadIdx.x & 31;
    const int wloc = threadIdx.x >> 5;
    const int r    = lane >> 3;     // row-subgroup 0..3
    const int c    = lane & 7;      // column quad 0..7
    const int base = (blockIdx.x * WARPS_PER_BLOCK + wloc) * CELLS_PER_WARP;

#pragma unroll 2
    for (int j = 0; j < CELLS_PER_WARP; ++j) {
        const int cell = base + j;

        // Lane l holds x[l] for this cell (coalesced 128B per warp).
        const float xreg = x[(size_t)cell * NDIM + lane];

        // ---- Stage 1: act[l] = sum_k x[k] * M[k][l] ----
        const float4* __restrict__ M4 = input_matrix + (size_t)cell * MAT_F4;
        float4 acc = make_float4(0.f, 0.f, 0.f, 0.f);
#pragma unroll
        for (int i = 0; i < 8; ++i) {
            const int k = i * 4 + r;
            const float4 m = __ldcs(&M4[k * 8 + c]);      // 512B coalesced
            const float xv = __shfl_sync(FULLMASK, xreg, k);
            acc.x = fmaf(xv, m.x, acc.x);
            acc.y = fmaf(xv, m.y, acc.y);
            acc.z = fmaf(xv, m.z, acc.z);
            acc.w = fmaf(xv, m.w, acc.w);
        }
        reduce_xor(acc);

        // sel = act[4c + r]  (component r of this lane's reduced quad)
        const float sel = (r == 0) ? acc.x : (r == 1) ? acc.y
                         : (r == 2) ? acc.z : acc.w;

        // ---- Stage 2: acc2[l] = sum_d sum_n act[n] * W_d[n][l] ----
        // i-outer / d-inner: one broadcast shfl per i, reused for 4 dirs.
        float4 acc2 = make_float4(0.f, 0.f, 0.f, 0.f);
        const float4* __restrict__ Wc = layer_weights + (size_t)cell * MAT_F4;
#pragma unroll
        for (int i = 0; i < 8; ++i) {
            const int n = i * 4 + r;
            const float av = __shfl_sync(FULLMASK, sel, (r << 3) + i);
#pragma unroll
            for (int d = 0; d < 4; ++d) {
                const float4 w = __ldcs(&Wc[(size_t)d * NCELLS * MAT_F4 + n * 8 + c]);
                acc2.x = fmaf(av, w.x, acc2.x);
                acc2.y = fmaf(av, w.y, acc2.y);
                acc2.z = fmaf(av, w.z, acc2.z);
                acc2.w = fmaf(av, w.w, acc2.w);
            }
        }
        reduce_xor(acc2);

        if (r == 0) {
            acc2.x *= DECAY; acc2.y *= DECAY; acc2.z *= DECAY; acc2.w *= DECAY;
            out[(size_t)cell * 8 + c] = acc2;             // 128B coalesced
        }
    }
}

extern "C" void kernel_launch(void* const* d_in, const int* in_sizes, int n_in,
                              void* d_out, int out_size)
{
    const float*  x  = (const float*)d_in[0];
    const float4* im = (const float4*)d_in[1];
    const float4* lw = (const float4*)d_in[2];
    float4* out      = (float4*)d_out;

    snn_layer_kernel<<<BLOCKS, THREADS>>>(x, im, lw, out);
}

// round 5
// speedup vs baseline: 1.0774x; 1.0774x over previous
#include <cuda_runtime.h>

// SNNLayer, R5: R3 dataflow (best: 186.9us, DRAM 92.3%) with 128-thread
// blocks for finer CTA retire/wave granularity. Per-warp code identical to
// R3 — one cell per warp, barrier-free, smem-free, all-SHFL cross-lane.
//
//   d_in[0] x              : (256,256,1,32)
//   d_in[1] input_matrix   : (256,256,32,32)
//   d_in[2] layer_weights  : (4,256,256,32,32)
//   out                    : (256,256,1,32)
//
// Lane l = (r=l>>3, c=l&7). Stage-1 reduce (xor 8,16) leaves every lane the
// full quad act[4c..4c+3]; component r at lane (r,c) is act[4c+r]; stage 2
// broadcasts act[4i+r] = shfl(sel, r*8+i). No barriers, so ptxas hoists the
// 32 stage-2 LDG.128s above the stage-1 shfl-reduction chain.

#define NCELLS   65536
#define NDIM     32
#define MAT_F4   256            // 1024 floats = 256 float4
#define WARPS_PER_BLOCK 4
#define THREADS  (WARPS_PER_BLOCK * 32)      // 128
#define BLOCKS   (NCELLS / WARPS_PER_BLOCK)  // 16384
#define DECAY    0.8f
#define FULLMASK 0xFFFFFFFFu

__device__ __forceinline__ void reduce_xor(float4& a)
{
#pragma unroll
    for (int m = 8; m <= 16; m <<= 1) {
        a.x += __shfl_xor_sync(FULLMASK, a.x, m);
        a.y += __shfl_xor_sync(FULLMASK, a.y, m);
        a.z += __shfl_xor_sync(FULLMASK, a.z, m);
        a.w += __shfl_xor_sync(FULLMASK, a.w, m);
    }
}

__global__ __launch_bounds__(THREADS, 8)
void snn_layer_kernel(const float* __restrict__ x,
                      const float4* __restrict__ input_matrix,
                      const float4* __restrict__ layer_weights,
                      float4* __restrict__ out)
{
    const int lane = threadIdx.x & 31;
    const int wloc = threadIdx.x >> 5;
    const int r    = lane >> 3;     // row-subgroup 0..3
    const int c    = lane & 7;      // column quad 0..7
    const int cell = blockIdx.x * WARPS_PER_BLOCK + wloc;

    // Lane l holds x[l] for this cell (coalesced 128B per warp).
    const float xreg = x[(size_t)cell * NDIM + lane];

    // ---- Stage 1: act[l] = sum_k x[k] * M[k][l] ----
    const float4* __restrict__ M4 = input_matrix + (size_t)cell * MAT_F4;
    float4 acc = make_float4(0.f, 0.f, 0.f, 0.f);
#pragma unroll
    for (int i = 0; i < 8; ++i) {
        const int k = i * 4 + r;
        const float4 m = __ldcs(&M4[k * 8 + c]);      // 512B coalesced
        const float xv = __shfl_sync(FULLMASK, xreg, k);
        acc.x = fmaf(xv, m.x, acc.x);
        acc.y = fmaf(xv, m.y, acc.y);
        acc.z = fmaf(xv, m.z, acc.z);
        acc.w = fmaf(xv, m.w, acc.w);
    }
    reduce_xor(acc);

    // sel = act[4c + r]  (component r of this lane's reduced quad)
    const float sel = (r == 0) ? acc.x : (r == 1) ? acc.y
                     : (r == 2) ? acc.z : acc.w;

    // Broadcast: av[i] = act[4i + r]  (component r of quad i, lane r*8+i)
    float av[8];
#pragma unroll
    for (int i = 0; i < 8; ++i)
        av[i] = __shfl_sync(FULLMASK, sel, (r << 3) + i);

    // ---- Stage 2: acc2[l] = sum_d sum_n act[n] * W_d[n][l] ----
    float4 acc2 = make_float4(0.f, 0.f, 0.f, 0.f);
    const float4* __restrict__ Wc = layer_weights + (size_t)cell * MAT_F4;
#pragma unroll
    for (int d = 0; d < 4; ++d) {
        const float4* __restrict__ Wd = Wc + (size_t)d * NCELLS * MAT_F4;
#pragma unroll
        for (int i = 0; i < 8; ++i) {
            const int n = i * 4 + r;
            const float4 w = __ldcs(&Wd[n * 8 + c]);  // independent of stage 1
            acc2.x = fmaf(av[i], w.x, acc2.x);
            acc2.y = fmaf(av[i], w.y, acc2.y);
            acc2.z = fmaf(av[i], w.z, acc2.z);
            acc2.w = fmaf(av[i], w.w, acc2.w);
        }
    }
    reduce_xor(acc2);

    if (r == 0) {
        acc2.x *= DECAY; acc2.y *= DECAY; acc2.z *= DECAY; acc2.w *= DECAY;
        out[(size_t)cell * 8 + c] = acc2;             // 128B coalesced
    }
}

extern "C" void kernel_launch(void* const* d_in, const int* in_sizes, int n_in,
                              void* d_out, int out_size)
{
    const float*  x  = (const float*)d_in[0];
    const float4* im = (const float4*)d_in[1];
    const float4* lw = (const float4*)d_in[2];
    float4* out      = (float4*)d_out;

    snn_layer_kernel<<<BLOCKS, THREADS>>>(x, im, lw, out);
}